// round 1
// baseline (speedup 1.0000x reference)
#include <cuda_runtime.h>

typedef unsigned long long ull;

// ---------------- packed f32x2 helpers (FFMA2) ----------------
__device__ __forceinline__ ull fma2(ull a, ull b, ull c) {
    ull d;
    asm("fma.rn.f32x2 %0, %1, %2, %3;" : "=l"(d) : "l"(a), "l"(b), "l"(c));
    return d;
}
__device__ __forceinline__ ull pk2(float lo, float hi) {
    ull r;
    asm("mov.b64 %0, {%1, %2};" : "=l"(r) : "f"(lo), "f"(hi));
    return r;
}
__device__ __forceinline__ float2 up2(ull a) {
    float2 v;
    asm("mov.b64 {%0, %1}, %2;" : "=f"(v.x), "=f"(v.y) : "l"(a));
    return v;
}

// ---------------- constants ----------------
constexpr int   DDIM    = 64;
constexpr int   ROWS    = 64;      // rows per block
constexpr int   THREADS = 256;
constexpr float HSTEP   = 0.05f;   // 0.5 * dt_eff
constexpr float DT_EFF  = 0.1f;
constexpr float CMU     = 0.0025f; // h * FRICTION_SCALE
constexpr float TWO_PI     = 6.2831853071795864769f;
constexpr float INV_TWO_PI = 0.15915494309189533577f;

// shared strides (floats)
constexpr int SRS = 66;  // padded row stride for scalar state arrays

// shared layout sizes (bytes)
constexpr int SZ_STATE = ROWS * SRS * 4;      // one [64][66] float array: 16896
constexpr int SMEM_BYTES =
    4 * SZ_STATE            // sX, sV, sF, sMu(rden)
  + ROWS * 64 * 8           // sSC  float2 [64][64]
  + ROWS * 18 * 4           // sA2  float  [64][18]
  + 32 * 16 * 8             // sUp  float2 [32][16]
  + 8 * 64 * 8              // sWp  float2 [8][64]
  + 64 * 64 * 8             // sWfp float2 [64][64]
  + 64 * 4;                 // sBf

__global__ void __launch_bounds__(THREADS, 1)
leapfrog_kernel(const float* __restrict__ x_in,
                const float* __restrict__ v_in,
                const float* __restrict__ f_in,
                const float* __restrict__ U_in,
                const float* __restrict__ W_in,
                const float* __restrict__ Wf_in,
                const float* __restrict__ bf_in,
                const int*   __restrict__ steps_ptr,
                float* __restrict__ out,
                int Btot)
{
    extern __shared__ char smraw[];
    float*  sX   = (float*)smraw;                 // [64][66]
    float*  sV   = sX  + ROWS * SRS;              // [64][66]
    float*  sF   = sV  + ROWS * SRS;              // [64][66]
    float*  sMu  = sF  + ROWS * SRS;              // [64][66]  holds rden = 1/(1+h*mu)
    float2* sSC  = (float2*)(sMu + ROWS * SRS);   // [64][64]  (sin, cos)
    float*  sA2  = (float*)(sSC + ROWS * 64);     // [64][18]
    float2* sUp  = (float2*)(sA2 + ROWS * 18);    // [32][16]  (U[r][2d], U[r][2d+1]) at [d2][r]
    float2* sWp  = sUp + 32 * 16;                 // [8][64]   (W[2r][c], W[2r+1][c]) at [r2][c]
    float2* sWfp = sWp + 8 * 64;                  // [64][64]  (Wf[c][j], Wf[c][64+j]) at [j][c]
    float*  sBf  = (float*)(sWfp + 64 * 64);      // [64]

    const int tid = threadIdx.x;
    const int w   = tid >> 5;   // warp id: owns rows [8w, 8w+8)
    const int l   = tid & 31;   // lane: owns cols {2l, 2l+1}
    const int rowBase = blockIdx.x * ROWS;

    // -------- P0: load state + weights --------
    #pragma unroll
    for (int i = tid; i < ROWS * 16; i += THREADS) {
        int r = i >> 4, c = (i & 15) << 2;
        int g = (rowBase + r) * DDIM + c;
        float4 a = *(const float4*)(x_in + g);
        float4 b = *(const float4*)(v_in + g);
        float4 cfv = *(const float4*)(f_in + g);
        float* px = sX + r * SRS + c;
        float* pv = sV + r * SRS + c;
        float* pf = sF + r * SRS + c;
        px[0]=a.x; px[1]=a.y; px[2]=a.z; px[3]=a.w;
        pv[0]=b.x; pv[1]=b.y; pv[2]=b.z; pv[3]=b.w;
        pf[0]=cfv.x; pf[1]=cfv.y; pf[2]=cfv.z; pf[3]=cfv.w;
    }
    #pragma unroll
    for (int i = tid; i < 512; i += THREADS) {       // U: [16][64]
        int d2 = i >> 4, r = i & 15;
        sUp[i] = make_float2(U_in[r * 64 + 2 * d2], U_in[r * 64 + 2 * d2 + 1]);
    }
    #pragma unroll
    for (int i = tid; i < 512; i += THREADS) {       // W: [16][64]
        int r2 = i >> 6, c = i & 63;
        sWp[i] = make_float2(W_in[(2 * r2) * 64 + c], W_in[(2 * r2 + 1) * 64 + c]);
    }
    #pragma unroll
    for (int i = tid; i < 4096; i += THREADS) {      // Wf: [64][128]
        int c = i >> 6, j = i & 63;
        sWfp[j * 64 + c] = make_float2(Wf_in[c * 128 + j], Wf_in[c * 128 + 64 + j]);
    }
    if (tid < 64) sBf[tid] = bf_in[tid];
    __syncthreads();

    // -------- P1: initial sincos of x --------
    #pragma unroll
    for (int i = tid; i < ROWS * DDIM; i += THREADS) {
        int r = i >> 6, c = i & 63;
        float s, cc;
        __sincosf(sX[r * SRS + c], &s, &cc);
        sSC[r * 64 + c] = make_float2(s, cc);
    }
    __syncthreads();

    // -------- friction: gate GEMM + sigmoid -> rden --------
    auto friction = [&]() {
        ull acc0[8], acc1[8];
        #pragma unroll
        for (int r = 0; r < 8; r++) { acc0[r] = 0ull; acc1[r] = 0ull; }
        const float2* scBase = sSC + w * 8 * 64;
        #pragma unroll 4
        for (int j = 0; j < 64; j++) {
            float4 wv = *(const float4*)(sWfp + j * 64 + 2 * l);
            ull b0 = pk2(wv.x, wv.y), b1 = pk2(wv.z, wv.w);
            #pragma unroll
            for (int r = 0; r < 8; r++) {
                ull sc = *(const ull*)(scBase + r * 64 + j);    // broadcast
                acc0[r] = fma2(sc, b0, acc0[r]);
                acc1[r] = fma2(sc, b1, acc1[r]);
            }
        }
        const float bA = sBf[2 * l], bB = sBf[2 * l + 1];
        #pragma unroll
        for (int r = 0; r < 8; r++) {
            int row = w * 8 + r;
            float2 g0 = up2(acc0[r]);
            float2 g1 = up2(acc1[r]);
            float gate0 = g0.x + g0.y + bA;
            float gate1 = g1.x + g1.y + bB;
            float t0 = 1.0f + __expf(-gate0);
            float t1 = 1.0f + __expf(-gate1);
            float rd0 = t0 * __frcp_rn(t0 + CMU);
            float rd1 = t1 * __frcp_rn(t1 + CMU);
            *(float2*)(sMu + row * SRS + 2 * l) = make_float2(rd0, rd1);
        }
    };

    // -------- gemm1: a2 = (v @ U^T)^2 --------
    auto gemm1 = [&]() {
        const int rh = l >> 4, r = l & 15;
        const int row0 = w * 8 + rh * 4;
        ull acc[4];
        #pragma unroll
        for (int k = 0; k < 4; k++) acc[k] = 0ull;
        #pragma unroll 4
        for (int d2 = 0; d2 < 32; d2++) {
            ull u = *(const ull*)(sUp + d2 * 16 + r);
            #pragma unroll
            for (int k = 0; k < 4; k++) {
                ull vv = *(const ull*)(sV + (row0 + k) * SRS + 2 * d2);
                acc[k] = fma2(vv, u, acc[k]);
            }
        }
        #pragma unroll
        for (int k = 0; k < 4; k++) {
            float2 p = up2(acc[k]);
            float a = p.x + p.y;
            sA2[(row0 + k) * 18 + r] = a * a;
        }
    };

    // -------- gemm2 + velocity/position update --------
    auto gemm2up = [&](bool half1) {
        ull acc0[8], acc1[8];
        #pragma unroll
        for (int r = 0; r < 8; r++) { acc0[r] = 0ull; acc1[r] = 0ull; }
        const float* a2Base = sA2 + w * 8 * 18;
        #pragma unroll
        for (int r2 = 0; r2 < 8; r2++) {
            float4 wv = *(const float4*)(sWp + r2 * 64 + 2 * l);
            ull b0 = pk2(wv.x, wv.y), b1 = pk2(wv.z, wv.w);
            #pragma unroll
            for (int rr = 0; rr < 8; rr++) {
                ull ap = *(const ull*)(a2Base + rr * 18 + 2 * r2);  // broadcast
                acc0[rr] = fma2(ap, b0, acc0[rr]);
                acc1[rr] = fma2(ap, b1, acc1[rr]);
            }
        }
        #pragma unroll
        for (int rr = 0; rr < 8; rr++) {
            int row = w * 8 + rr;
            float2 pa = up2(acc0[rr]);
            float2 pb = up2(acc1[rr]);
            float gam0 = pa.x + pa.y;
            float gam1 = pb.x + pb.y;
            float2 vv = *(const float2*)(sV  + row * SRS + 2 * l);
            float2 ff = *(const float2*)(sF  + row * SRS + 2 * l);
            float2 rd = *(const float2*)(sMu + row * SRS + 2 * l);
            float vh0 = (vv.x + HSTEP * (ff.x - gam0)) * rd.x;
            float vh1 = (vv.y + HSTEP * (ff.y - gam1)) * rd.y;
            *(float2*)(sV + row * SRS + 2 * l) = make_float2(vh0, vh1);
            if (half1) {
                float2 xx = *(const float2*)(sX + row * SRS + 2 * l);
                xx.x = fmaf(DT_EFF, vh0, xx.x);
                xx.y = fmaf(DT_EFF, vh1, xx.y);
                *(float2*)(sX + row * SRS + 2 * l) = xx;
                float s0, c0, s1, c1;
                __sincosf(xx.x, &s0, &c0);
                __sincosf(xx.y, &s1, &c1);
                sSC[row * 64 + 2 * l]     = make_float2(s0, c0);
                sSC[row * 64 + 2 * l + 1] = make_float2(s1, c1);
            }
        }
    };

    // -------- P2: initial friction (for x0) --------
    friction();
    __syncthreads();

    // -------- main loop --------
    const int steps = steps_ptr[0];
    for (int s = 0; s < steps; s++) {
        gemm1();          __syncthreads();   // a2 from v
        gemm2up(true);    __syncthreads();   // v_half, x update, sincos(new x)
        friction();       __syncthreads();   // rden for new x (used now AND next step)
        gemm1();          __syncthreads();   // a2 from v_half
        gemm2up(false);   __syncthreads();   // final v
    }

    // -------- output: wrap x, write x then v --------
    #pragma unroll
    for (int i = tid; i < ROWS * DDIM; i += THREADS) {
        int r = i >> 6, c = i & 63;
        float xv = sX[r * SRS + c];
        xv = fmaf(-TWO_PI, rintf(xv * INV_TWO_PI), xv);   // == atan2(sin x, cos x)
        int g = (rowBase + r) * DDIM + c;
        out[g] = xv;
        out[Btot * DDIM + g] = sV[r * SRS + c];
    }
}

extern "C" void kernel_launch(void* const* d_in, const int* in_sizes, int n_in,
                              void* d_out, int out_size)
{
    const float* x  = (const float*)d_in[0];
    const float* v  = (const float*)d_in[1];
    const float* f  = (const float*)d_in[2];
    const float* U  = (const float*)d_in[3];
    const float* W  = (const float*)d_in[4];
    const float* Wf = (const float*)d_in[5];
    const float* bf = (const float*)d_in[6];
    const int* steps = (const int*)d_in[7];   // first 4 bytes give the value for i32/i64

    float* out = (float*)d_out;
    const int Btot = in_sizes[0] / DDIM;      // 262144
    const int blocks = Btot / ROWS;           // 4096

    cudaFuncSetAttribute(leapfrog_kernel,
                         cudaFuncAttributeMaxDynamicSharedMemorySize, SMEM_BYTES);
    leapfrog_kernel<<<blocks, THREADS, SMEM_BYTES>>>(x, v, f, U, W, Wf, bf, steps,
                                                     out, Btot);
}

// round 3
// speedup vs baseline: 3.9054x; 3.9054x over previous
#include <cuda_runtime.h>
#include <stdint.h>

constexpr int THREADS = 128;
constexpr float HSTEP  = 0.05f;     // 0.5 * dt_eff
constexpr float DT_EFF = 0.1f;
constexpr float CMU_H  = 0.00125f;  // 0.5 * h * FRICTION_SCALE
constexpr float TWO_PI     = 6.2831853071795864769f;
constexpr float INV_TWO_PI = 0.15915494309189533577f;

// ---------------- helpers ----------------
__device__ __forceinline__ uint32_t bf2(float lo, float hi){
    uint32_t r;
    asm("cvt.rn.bf16x2.f32 %0, %1, %2;" : "=r"(r) : "f"(hi), "f"(lo));
    return r;
}
// hi/lo bf16 split: x = hi + lo with |lo| <= 2^-8 |x|, residual err ~2^-17
__device__ __forceinline__ void split2(float x0, float x1, uint32_t& hi, uint32_t& lo){
    hi = bf2(x0, x1);
    float h0 = __uint_as_float(hi << 16);
    float h1 = __uint_as_float(hi & 0xFFFF0000u);
    lo = bf2(x0 - h0, x1 - h1);
}
__device__ __forceinline__ float tanha(float x){
    float y; asm("tanh.approx.f32 %0, %1;" : "=f"(y) : "f"(x)); return y;
}
// rden = 1/(1 + h*mu), h*mu = CMU_H*(1+tanh(g/2));  1/(1+z) ~= 1 - z + z^2 (z<=0.0025)
__device__ __forceinline__ float rdenf(float gate){
    float z = CMU_H * (1.0f + tanha(0.5f * gate));
    return fmaf(z, z, 1.0f) - z;
}
__device__ __forceinline__ void mma(float* c, uint32_t a0, uint32_t a1, uint32_t a2, uint32_t a3,
                                    uint32_t b0, uint32_t b1){
    asm("mma.sync.aligned.m16n8k16.row.col.f32.bf16.bf16.f32 "
        "{%0,%1,%2,%3}, {%4,%5,%6,%7}, {%8,%9}, {%0,%1,%2,%3};"
        : "+f"(c[0]), "+f"(c[1]), "+f"(c[2]), "+f"(c[3])
        : "r"(a0), "r"(a1), "r"(a2), "r"(a3), "r"(b0), "r"(b1));
}

// =====================================================================
// Thread (g = lane>>2, m = lane&3) owns rows {g, g+8} of its warp's 16-row
// block and columns col = 8s + 2m + e (s=0..7, e=0..1).
// State index: idx = rr*16 + 2s + e.
// This matches BOTH the mma.m16n8k16 A-fragment and C-fragment layouts,
// so all GEMM chaining is register-resident.
// =====================================================================
__global__ void __launch_bounds__(THREADS, 2)
leapfrog_mma_kernel(const float* __restrict__ x_in, const float* __restrict__ v_in,
                    const float* __restrict__ f_in, const float* __restrict__ U_in,
                    const float* __restrict__ W_in, const float* __restrict__ Wf_in,
                    const float* __restrict__ bf_in, const int* __restrict__ steps_ptr,
                    float* __restrict__ out, int Btot)
{
    // per-lane fragment tables (80B stride => conflict-free lds.128)
    __shared__ uint4 sWf[8 * 32 * 5];   // [kt][lane][4 uint4 + pad]: gate B-frags
    __shared__ uint4 sUl[32 * 5];       // [lane][4 kt + pad]: U lo-frags
    __shared__ uint4 sWl[32 * 5];       // [lane][4 j + pad]:  W lo-frags
    __shared__ float sBias[64];

    const int tid = threadIdx.x, wid = tid >> 5, lane = tid & 31;
    const int g = lane >> 2, m = lane & 3;
    const int rbase = blockIdx.x * 64 + wid * 16;
    const int r0 = rbase + g;

    // ---- gate B-fragment table: Wf [64][128], B[n][k] = Wf[n][k] ----
    #pragma unroll
    for (int t = 0; t < 2; t++) {
        int kt = wid + 4 * t;
        #pragma unroll
        for (int j = 0; j < 4; j++) {
            const float* w0 = Wf_in + (8 * (2 * j)     + g) * 128 + 16 * kt;
            const float* w1 = Wf_in + (8 * (2 * j + 1) + g) * 128 + 16 * kt;
            uint4 q;
            q.x = bf2(w0[2 * m],     w0[2 * m + 1]);
            q.y = bf2(w0[8 + 2 * m], w0[9 + 2 * m]);
            q.z = bf2(w1[2 * m],     w1[2 * m + 1]);
            q.w = bf2(w1[8 + 2 * m], w1[9 + 2 * m]);
            sWf[(kt * 32 + lane) * 5 + j] = q;
        }
    }

    // ---- U fragments: B[n=r][k=d] = U[r][d]; hi in regs, lo in smem ----
    uint32_t Uh[2][4][2];
    {
        uint4 qlo[4];
        #pragma unroll
        for (int kt = 0; kt < 4; kt++) {
            uint32_t lo[2][2];
            #pragma unroll
            for (int nt = 0; nt < 2; nt++) {
                const float* up = U_in + (8 * nt + g) * 64 + 16 * kt;
                split2(up[2 * m],     up[2 * m + 1], Uh[nt][kt][0], lo[nt][0]);
                split2(up[8 + 2 * m], up[9 + 2 * m], Uh[nt][kt][1], lo[nt][1]);
            }
            qlo[kt] = make_uint4(lo[0][0], lo[0][1], lo[1][0], lo[1][1]);
        }
        if (wid == 0) {
            #pragma unroll
            for (int kt = 0; kt < 4; kt++) sUl[lane * 5 + kt] = qlo[kt];
        }
    }

    // ---- W fragments: B[n][k=r] = W[r][n]; hi in regs, lo in smem ----
    uint32_t Wh[8][2];
    {
        uint4 qlo[4];
        #pragma unroll
        for (int j = 0; j < 4; j++) {
            uint32_t lo[2][2];
            #pragma unroll
            for (int u = 0; u < 2; u++) {
                int nt = 2 * j + u, n = 8 * nt + g;
                split2(W_in[(2 * m) * 64 + n],     W_in[(2 * m + 1) * 64 + n], Wh[nt][0], lo[u][0]);
                split2(W_in[(2 * m + 8) * 64 + n], W_in[(2 * m + 9) * 64 + n], Wh[nt][1], lo[u][1]);
            }
            qlo[j] = make_uint4(lo[0][0], lo[0][1], lo[1][0], lo[1][1]);
        }
        if (wid == 0) {
            #pragma unroll
            for (int j = 0; j < 4; j++) sWl[lane * 5 + j] = qlo[j];
        }
    }
    if (tid < 64) sBias[tid] = bf_in[tid];

    // ---- state into registers ----
    float xr[32], vr[32], fr[32], rden[32];
    #pragma unroll
    for (int rr = 0; rr < 2; rr++) {
        const size_t base = (size_t)(r0 + 8 * rr) * 64 + 2 * m;
        #pragma unroll
        for (int s = 0; s < 8; s++) {
            float2 t;
            t = *(const float2*)(x_in + base + 8 * s); xr[rr * 16 + 2 * s] = t.x; xr[rr * 16 + 2 * s + 1] = t.y;
            t = *(const float2*)(v_in + base + 8 * s); vr[rr * 16 + 2 * s] = t.x; vr[rr * 16 + 2 * s + 1] = t.y;
            t = *(const float2*)(f_in + base + 8 * s); fr[rr * 16 + 2 * s] = t.x; fr[rr * 16 + 2 * s + 1] = t.y;
        }
    }
    __syncthreads();   // the only barrier; loop below is barrier-free

    uint32_t sbf[16], cbf[16];
    float aC[2][4];
    float gamC[8][4];

    // ---- features: sincos of current x, packed bf16x2 ----
    auto featpack = [&]() {
        #pragma unroll
        for (int i = 0; i < 16; i++) {
            float s0, c0, s1, c1;
            __sincosf(xr[2 * i],     &s0, &c0);
            __sincosf(xr[2 * i + 1], &s1, &c1);
            sbf[i] = bf2(s0, s1);
            cbf[i] = bf2(c0, c1);
        }
    };

    // ---- gate GEMM (plain bf16) + rden epilogue ----
    auto gate_rden = [&]() {
        float gc[8][4];
        #pragma unroll
        for (int nt = 0; nt < 8; nt++)
            #pragma unroll
            for (int k = 0; k < 4; k++) gc[nt][k] = 0.0f;
        #pragma unroll
        for (int kt = 0; kt < 8; kt++) {
            uint32_t a0, a1, a2, a3;
            if (kt < 4) { a0 = sbf[2 * kt]; a1 = sbf[8 + 2 * kt]; a2 = sbf[2 * kt + 1]; a3 = sbf[9 + 2 * kt]; }
            else { int k = kt - 4; a0 = cbf[2 * k]; a1 = cbf[8 + 2 * k]; a2 = cbf[2 * k + 1]; a3 = cbf[9 + 2 * k]; }
            #pragma unroll
            for (int j = 0; j < 4; j++) {
                uint4 q = sWf[(kt * 32 + lane) * 5 + j];
                mma(gc[2 * j],     a0, a1, a2, a3, q.x, q.y);
                mma(gc[2 * j + 1], a0, a1, a2, a3, q.z, q.w);
            }
        }
        #pragma unroll
        for (int nt = 0; nt < 8; nt++) {
            float2 bb = *(const float2*)(sBias + 8 * nt + 2 * m);
            rden[2 * nt]      = rdenf(gc[nt][0] + bb.x);
            rden[2 * nt + 1]  = rdenf(gc[nt][1] + bb.y);
            rden[16 + 2 * nt] = rdenf(gc[nt][2] + bb.x);
            rden[17 + 2 * nt] = rdenf(gc[nt][3] + bb.y);
        }
    };

    // ---- gemm1: a = v . U^T (bf16 hi/lo, 3 products) ----
    auto g1 = [&]() {
        #pragma unroll
        for (int nt = 0; nt < 2; nt++)
            #pragma unroll
            for (int k = 0; k < 4; k++) aC[nt][k] = 0.0f;
        #pragma unroll
        for (int kt = 0; kt < 4; kt++) {
            uint32_t ah0, ah1, ah2, ah3, al0, al1, al2, al3;
            split2(vr[4 * kt],      vr[4 * kt + 1],  ah0, al0);
            split2(vr[16 + 4 * kt], vr[17 + 4 * kt], ah1, al1);
            split2(vr[4 * kt + 2],  vr[4 * kt + 3],  ah2, al2);
            split2(vr[18 + 4 * kt], vr[19 + 4 * kt], ah3, al3);
            uint4 ql = sUl[lane * 5 + kt];
            uint32_t Ulf[2][2] = {{ql.x, ql.y}, {ql.z, ql.w}};
            #pragma unroll
            for (int nt = 0; nt < 2; nt++) {
                mma(aC[nt], ah0, ah1, ah2, ah3, Uh[nt][kt][0], Uh[nt][kt][1]);
                mma(aC[nt], ah0, ah1, ah2, ah3, Ulf[nt][0],    Ulf[nt][1]);
                mma(aC[nt], al0, al1, al2, al3, Uh[nt][kt][0], Uh[nt][kt][1]);
            }
        }
    };

    // ---- gemm2: gamma = (a*a) . W (bf16 hi/lo) ----
    auto g2 = [&]() {
        uint32_t h0, h1, h2, h3, l0, l1, l2, l3;
        split2(aC[0][0] * aC[0][0], aC[0][1] * aC[0][1], h0, l0);
        split2(aC[0][2] * aC[0][2], aC[0][3] * aC[0][3], h1, l1);
        split2(aC[1][0] * aC[1][0], aC[1][1] * aC[1][1], h2, l2);
        split2(aC[1][2] * aC[1][2], aC[1][3] * aC[1][3], h3, l3);
        #pragma unroll
        for (int j = 0; j < 4; j++) {
            uint4 ql = sWl[lane * 5 + j];
            uint32_t Wlf[2][2] = {{ql.x, ql.y}, {ql.z, ql.w}};
            #pragma unroll
            for (int u = 0; u < 2; u++) {
                int nt = 2 * j + u;
                #pragma unroll
                for (int k = 0; k < 4; k++) gamC[nt][k] = 0.0f;
                mma(gamC[nt], h0, h1, h2, h3, Wh[nt][0], Wh[nt][1]);
                mma(gamC[nt], h0, h1, h2, h3, Wlf[u][0], Wlf[u][1]);
                mma(gamC[nt], l0, l1, l2, l3, Wh[nt][0], Wh[nt][1]);
            }
        }
    };

    // ---- velocity (and position) update ----
    auto half = [&](bool first) {
        #pragma unroll
        for (int nt = 0; nt < 8; nt++) {
            int idx[4] = {2 * nt, 2 * nt + 1, 16 + 2 * nt, 17 + 2 * nt};
            #pragma unroll
            for (int k = 0; k < 4; k++) {
                int i = idx[k];
                float vn = (vr[i] + HSTEP * (fr[i] - gamC[nt][k])) * rden[i];
                vr[i] = vn;
                if (first) xr[i] = fmaf(DT_EFF, vn, xr[i]);
            }
        }
    };

    // ---- initial friction at x0 ----
    featpack();
    gate_rden();

    // ---- main loop (barrier-free) ----
    const int steps = steps_ptr[0];
    for (int s = 0; s < steps; s++) {
        g1(); g2(); half(true);        // v_half, x update   (rden = mu at old x)
        featpack(); gate_rden();       // mu at new x (used for half2 AND next step)
        g1(); g2(); half(false);       // final v of the step
    }

    // ---- output: wrap x, write x then v ----
    #pragma unroll
    for (int rr = 0; rr < 2; rr++) {
        const size_t base = (size_t)(r0 + 8 * rr) * 64 + 2 * m;
        #pragma unroll
        for (int s = 0; s < 8; s++) {
            float X0 = xr[rr * 16 + 2 * s], X1 = xr[rr * 16 + 2 * s + 1];
            float2 qx;
            qx.x = fmaf(-TWO_PI, rintf(X0 * INV_TWO_PI), X0);
            qx.y = fmaf(-TWO_PI, rintf(X1 * INV_TWO_PI), X1);
            *(float2*)(out + base + 8 * s) = qx;
            float2 qv = make_float2(vr[rr * 16 + 2 * s], vr[rr * 16 + 2 * s + 1]);
            *(float2*)(out + (size_t)Btot * 64 + base + 8 * s) = qv;
        }
    }
}

extern "C" void kernel_launch(void* const* d_in, const int* in_sizes, int n_in,
                              void* d_out, int out_size)
{
    const float* x  = (const float*)d_in[0];
    const float* v  = (const float*)d_in[1];
    const float* f  = (const float*)d_in[2];
    const float* U  = (const float*)d_in[3];
    const float* W  = (const float*)d_in[4];
    const float* Wf = (const float*)d_in[5];
    const float* bf = (const float*)d_in[6];
    const int* steps = (const int*)d_in[7];

    float* out = (float*)d_out;
    const int Btot = in_sizes[0] / 64;     // 262144
    const int blocks = Btot / 64;          // 4096 (64 rows per CTA, 4 warps)

    leapfrog_mma_kernel<<<blocks, THREADS>>>(x, v, f, U, W, Wf, bf, steps, out, Btot);
}

// round 4
// speedup vs baseline: 3.9863x; 1.0207x over previous
#include <cuda_runtime.h>
#include <stdint.h>

constexpr int THREADS = 128;
constexpr float HSTEP  = 0.05f;     // 0.5 * dt_eff
constexpr float DT_EFF = 0.1f;
constexpr float CMU_H  = 0.00125f;  // 0.5 * h * FRICTION_SCALE
constexpr float TWO_PI     = 6.2831853071795864769f;
constexpr float INV_TWO_PI = 0.15915494309189533577f;

// ---------------- helpers ----------------
__device__ __forceinline__ uint32_t bf2(float lo, float hi){
    uint32_t r;
    asm("cvt.rn.bf16x2.f32 %0, %1, %2;" : "=r"(r) : "f"(hi), "f"(lo));
    return r;
}
// hi/lo bf16 split: x = hi + lo with |lo| <= 2^-8 |x|, residual err ~2^-17
__device__ __forceinline__ void split2(float x0, float x1, uint32_t& hi, uint32_t& lo){
    hi = bf2(x0, x1);
    float h0 = __uint_as_float(hi << 16);
    float h1 = __uint_as_float(hi & 0xFFFF0000u);
    lo = bf2(x0 - h0, x1 - h1);
}
__device__ __forceinline__ float tanha(float x){
    float y; asm("tanh.approx.f32 %0, %1;" : "=f"(y) : "f"(x)); return y;
}
// rden = 1/(1 + h*mu), h*mu = CMU_H*(1+tanh(g/2));  1/(1+z) ~= 1 - z + z^2 (z<=0.0025)
__device__ __forceinline__ float rdenf(float gate){
    float z = CMU_H * (1.0f + tanha(0.5f * gate));
    return fmaf(z, z, 1.0f) - z;
}
__device__ __forceinline__ void mma(float* c, uint32_t a0, uint32_t a1, uint32_t a2, uint32_t a3,
                                    uint32_t b0, uint32_t b1){
    asm("mma.sync.aligned.m16n8k16.row.col.f32.bf16.bf16.f32 "
        "{%0,%1,%2,%3}, {%4,%5,%6,%7}, {%8,%9}, {%0,%1,%2,%3};"
        : "+f"(c[0]), "+f"(c[1]), "+f"(c[2]), "+f"(c[3])
        : "r"(a0), "r"(a1), "r"(a2), "r"(a3), "r"(b0), "r"(b1));
}

// =====================================================================
// Thread (g = lane>>2, m = lane&3) owns rows {g, g+8} of its warp's 16-row
// block and columns col = 8s + 2m + e.  State idx = rr*16 + 2s + e.
// Matches both mma.m16n8k16 A- and C-fragment layouts: all GEMM chaining
// is register-resident, main loop is barrier-free.
// =====================================================================
__global__ void __launch_bounds__(THREADS, 2)
leapfrog_mma_kernel(const float* __restrict__ x_in, const float* __restrict__ v_in,
                    const float* __restrict__ f_in, const float* __restrict__ U_in,
                    const float* __restrict__ W_in, const float* __restrict__ Wf_in,
                    const float* __restrict__ bf_in, const int* __restrict__ steps_ptr,
                    float* __restrict__ out, int Btot)
{
    // per-lane fragment tables (80B stride => conflict-free lds.128)
    __shared__ uint4 sWf[8 * 32 * 5];   // [kt][lane][4 uint4 + pad]: gate B-frags
    __shared__ uint4 sUl[32 * 5];       // [lane][4 kt + pad]: U lo-frags
    __shared__ uint4 sWl[32 * 5];       // [lane][4 j + pad]:  W lo-frags
    __shared__ float sBias[64];

    const int tid = threadIdx.x, wid = tid >> 5, lane = tid & 31;
    const int g = lane >> 2, m = lane & 3;
    const int r0 = blockIdx.x * 64 + wid * 16 + g;

    // ---- gate B-fragment table: Wf [64][128], B[n][k] = Wf[n][k] ----
    #pragma unroll
    for (int t = 0; t < 2; t++) {
        int kt = wid + 4 * t;
        #pragma unroll
        for (int j = 0; j < 4; j++) {
            const float* w0 = Wf_in + (8 * (2 * j)     + g) * 128 + 16 * kt;
            const float* w1 = Wf_in + (8 * (2 * j + 1) + g) * 128 + 16 * kt;
            uint4 q;
            q.x = bf2(w0[2 * m],     w0[2 * m + 1]);
            q.y = bf2(w0[8 + 2 * m], w0[9 + 2 * m]);
            q.z = bf2(w1[2 * m],     w1[2 * m + 1]);
            q.w = bf2(w1[8 + 2 * m], w1[9 + 2 * m]);
            sWf[(kt * 32 + lane) * 5 + j] = q;
        }
    }

    // ---- U fragments: B[n=r][k=d] = U[r][d]; hi in regs, lo in smem ----
    uint32_t Uh[2][4][2];
    {
        uint4 qlo[4];
        #pragma unroll
        for (int kt = 0; kt < 4; kt++) {
            uint32_t lo[2][2];
            #pragma unroll
            for (int nt = 0; nt < 2; nt++) {
                const float* up = U_in + (8 * nt + g) * 64 + 16 * kt;
                split2(up[2 * m],     up[2 * m + 1], Uh[nt][kt][0], lo[nt][0]);
                split2(up[8 + 2 * m], up[9 + 2 * m], Uh[nt][kt][1], lo[nt][1]);
            }
            qlo[kt] = make_uint4(lo[0][0], lo[0][1], lo[1][0], lo[1][1]);
        }
        if (wid == 0) {
            #pragma unroll
            for (int kt = 0; kt < 4; kt++) sUl[lane * 5 + kt] = qlo[kt];
        }
    }

    // ---- W fragments: B[n][k=r] = W[r][n]; hi in regs, lo in smem ----
    uint32_t Wh[8][2];
    {
        uint4 qlo[4];
        #pragma unroll
        for (int j = 0; j < 4; j++) {
            uint32_t lo[2][2];
            #pragma unroll
            for (int u = 0; u < 2; u++) {
                int nt = 2 * j + u, n = 8 * nt + g;
                split2(W_in[(2 * m) * 64 + n],     W_in[(2 * m + 1) * 64 + n], Wh[nt][0], lo[u][0]);
                split2(W_in[(2 * m + 8) * 64 + n], W_in[(2 * m + 9) * 64 + n], Wh[nt][1], lo[u][1]);
            }
            qlo[j] = make_uint4(lo[0][0], lo[0][1], lo[1][0], lo[1][1]);
        }
        if (wid == 0) {
            #pragma unroll
            for (int j = 0; j < 4; j++) sWl[lane * 5 + j] = qlo[j];
        }
    }
    if (tid < 64) sBias[tid] = bf_in[tid];

    // ---- state into registers ----
    float xr[32], vr[32], fr[32], rden[32];
    #pragma unroll
    for (int rr = 0; rr < 2; rr++) {
        const size_t base = (size_t)(r0 + 8 * rr) * 64 + 2 * m;
        #pragma unroll
        for (int s = 0; s < 8; s++) {
            float2 t;
            t = *(const float2*)(x_in + base + 8 * s); xr[rr * 16 + 2 * s] = t.x; xr[rr * 16 + 2 * s + 1] = t.y;
            t = *(const float2*)(v_in + base + 8 * s); vr[rr * 16 + 2 * s] = t.x; vr[rr * 16 + 2 * s + 1] = t.y;
            t = *(const float2*)(f_in + base + 8 * s); fr[rr * 16 + 2 * s] = t.x; fr[rr * 16 + 2 * s + 1] = t.y;
        }
    }
    __syncthreads();   // the only barrier; loop below is barrier-free

    float aC[2][4];
    float gamC[8][4];

    // ---- one g1 k-block with 3-way accumulators (chain depth 4) ----
    auto g1_block = [&](int kt, float aH[2][4], float aM[2][4], float aL[2][4]){
        uint32_t ah0, ah1, ah2, ah3, al0, al1, al2, al3;
        split2(vr[4 * kt],      vr[4 * kt + 1],  ah0, al0);
        split2(vr[16 + 4 * kt], vr[17 + 4 * kt], ah1, al1);
        split2(vr[4 * kt + 2],  vr[4 * kt + 3],  ah2, al2);
        split2(vr[18 + 4 * kt], vr[19 + 4 * kt], ah3, al3);
        uint4 ql = sUl[lane * 5 + kt];
        mma(aH[0], ah0, ah1, ah2, ah3, Uh[0][kt][0], Uh[0][kt][1]);
        mma(aH[1], ah0, ah1, ah2, ah3, Uh[1][kt][0], Uh[1][kt][1]);
        mma(aM[0], ah0, ah1, ah2, ah3, ql.x, ql.y);
        mma(aM[1], ah0, ah1, ah2, ah3, ql.z, ql.w);
        mma(aL[0], al0, al1, al2, al3, Uh[0][kt][0], Uh[0][kt][1]);
        mma(aL[1], al0, al1, al2, al3, Uh[1][kt][0], Uh[1][kt][1]);
    };

    // ---- standalone g1 (phase A) ----
    auto g1 = [&](){
        float aH[2][4], aM[2][4], aL[2][4];
        #pragma unroll
        for (int nt = 0; nt < 2; nt++)
            #pragma unroll
            for (int k = 0; k < 4; k++) { aH[nt][k] = 0.f; aM[nt][k] = 0.f; aL[nt][k] = 0.f; }
        #pragma unroll
        for (int kt = 0; kt < 4; kt++) g1_block(kt, aH, aM, aL);
        #pragma unroll
        for (int nt = 0; nt < 2; nt++)
            #pragma unroll
            for (int k = 0; k < 4; k++) aC[nt][k] = aH[nt][k] + aM[nt][k] + aL[nt][k];
    };

    // ---- fused: gate GEMM (+rden) interleaved with optional g1 ----
    // sincos computed inside the k-loop: sin used immediately, cos stashed.
    auto fused_gate = [&](bool with_g1){
        float gc[8][4];
        #pragma unroll
        for (int nt = 0; nt < 8; nt++)
            #pragma unroll
            for (int k = 0; k < 4; k++) gc[nt][k] = 0.0f;
        float aH[2][4], aM[2][4], aL[2][4];
        if (with_g1) {
            #pragma unroll
            for (int nt = 0; nt < 2; nt++)
                #pragma unroll
                for (int k = 0; k < 4; k++) { aH[nt][k] = 0.f; aM[nt][k] = 0.f; aL[nt][k] = 0.f; }
        }
        uint32_t cbf[16];
        #pragma unroll
        for (int kt = 0; kt < 8; kt++) {
            uint32_t a0, a1, a2, a3;
            if (kt < 4) {
                float s0, c0, s1, c1;
                __sincosf(xr[4 * kt],          &s0, &c0);
                __sincosf(xr[4 * kt + 1],      &s1, &c1);
                a0 = bf2(s0, s1); cbf[2 * kt] = bf2(c0, c1);
                __sincosf(xr[16 + 4 * kt],     &s0, &c0);
                __sincosf(xr[17 + 4 * kt],     &s1, &c1);
                a1 = bf2(s0, s1); cbf[8 + 2 * kt] = bf2(c0, c1);
                __sincosf(xr[4 * kt + 2],      &s0, &c0);
                __sincosf(xr[4 * kt + 3],      &s1, &c1);
                a2 = bf2(s0, s1); cbf[2 * kt + 1] = bf2(c0, c1);
                __sincosf(xr[18 + 4 * kt],     &s0, &c0);
                __sincosf(xr[19 + 4 * kt],     &s1, &c1);
                a3 = bf2(s0, s1); cbf[9 + 2 * kt] = bf2(c0, c1);
            } else {
                int k = kt - 4;
                a0 = cbf[2 * k]; a1 = cbf[8 + 2 * k]; a2 = cbf[2 * k + 1]; a3 = cbf[9 + 2 * k];
            }
            #pragma unroll
            for (int j = 0; j < 4; j++) {
                uint4 q = sWf[(kt * 32 + lane) * 5 + j];
                mma(gc[2 * j],     a0, a1, a2, a3, q.x, q.y);
                mma(gc[2 * j + 1], a0, a1, a2, a3, q.z, q.w);
            }
            if (with_g1 && kt < 4) g1_block(kt, aH, aM, aL);
        }
        if (with_g1) {
            #pragma unroll
            for (int nt = 0; nt < 2; nt++)
                #pragma unroll
                for (int k = 0; k < 4; k++) aC[nt][k] = aH[nt][k] + aM[nt][k] + aL[nt][k];
        }
        #pragma unroll
        for (int nt = 0; nt < 8; nt++) {
            float2 bb = *(const float2*)(sBias + 8 * nt + 2 * m);
            rden[2 * nt]      = rdenf(gc[nt][0] + bb.x);
            rden[2 * nt + 1]  = rdenf(gc[nt][1] + bb.y);
            rden[16 + 2 * nt] = rdenf(gc[nt][2] + bb.x);
            rden[17 + 2 * nt] = rdenf(gc[nt][3] + bb.y);
        }
    };

    // ---- gemm2: gamma = (a*a) . W (bf16 hi/lo, 8 parallel chains of 3) ----
    auto g2 = [&](){
        uint32_t h0, h1, h2, h3, l0, l1, l2, l3;
        split2(aC[0][0] * aC[0][0], aC[0][1] * aC[0][1], h0, l0);
        split2(aC[0][2] * aC[0][2], aC[0][3] * aC[0][3], h1, l1);
        split2(aC[1][0] * aC[1][0], aC[1][1] * aC[1][1], h2, l2);
        split2(aC[1][2] * aC[1][2], aC[1][3] * aC[1][3], h3, l3);
        #pragma unroll
        for (int j = 0; j < 4; j++) {
            uint4 ql = sWl[lane * 5 + j];
            uint32_t Wlf[2][2] = {{ql.x, ql.y}, {ql.z, ql.w}};
            #pragma unroll
            for (int u = 0; u < 2; u++) {
                int nt = 2 * j + u;
                #pragma unroll
                for (int k = 0; k < 4; k++) gamC[nt][k] = 0.0f;
                mma(gamC[nt], h0, h1, h2, h3, Wh[nt][0], Wh[nt][1]);
                mma(gamC[nt], h0, h1, h2, h3, Wlf[u][0], Wlf[u][1]);
                mma(gamC[nt], l0, l1, l2, l3, Wh[nt][0], Wh[nt][1]);
            }
        }
    };

    // ---- velocity (and position) update ----
    auto half = [&](bool first) {
        #pragma unroll
        for (int nt = 0; nt < 8; nt++) {
            int idx[4] = {2 * nt, 2 * nt + 1, 16 + 2 * nt, 17 + 2 * nt};
            #pragma unroll
            for (int k = 0; k < 4; k++) {
                int i = idx[k];
                float vn = (vr[i] + HSTEP * (fr[i] - gamC[nt][k])) * rden[i];
                vr[i] = vn;
                if (first) xr[i] = fmaf(DT_EFF, vn, xr[i]);
            }
        }
    };

    // ---- initial friction at x0 ----
    fused_gate(false);

    // ---- main loop (barrier-free) ----
    const int steps = steps_ptr[0];
    for (int s = 0; s < steps; s++) {
        g1(); g2(); half(true);        // v_half, x update (rden = mu at old x)
        fused_gate(true);              // mu(x_new) ∥ a(v_half)  — independent chains
        g2(); half(false);             // final v of the step
    }

    // ---- output: wrap x, write x then v ----
    #pragma unroll
    for (int rr = 0; rr < 2; rr++) {
        const size_t base = (size_t)(r0 + 8 * rr) * 64 + 2 * m;
        #pragma unroll
        for (int s = 0; s < 8; s++) {
            float X0 = xr[rr * 16 + 2 * s], X1 = xr[rr * 16 + 2 * s + 1];
            float2 qx;
            qx.x = fmaf(-TWO_PI, rintf(X0 * INV_TWO_PI), X0);
            qx.y = fmaf(-TWO_PI, rintf(X1 * INV_TWO_PI), X1);
            *(float2*)(out + base + 8 * s) = qx;
            float2 qv = make_float2(vr[rr * 16 + 2 * s], vr[rr * 16 + 2 * s + 1]);
            *(float2*)(out + (size_t)Btot * 64 + base + 8 * s) = qv;
        }
    }
}

extern "C" void kernel_launch(void* const* d_in, const int* in_sizes, int n_in,
                              void* d_out, int out_size)
{
    const float* x  = (const float*)d_in[0];
    const float* v  = (const float*)d_in[1];
    const float* f  = (const float*)d_in[2];
    const float* U  = (const float*)d_in[3];
    const float* W  = (const float*)d_in[4];
    const float* Wf = (const float*)d_in[5];
    const float* bf = (const float*)d_in[6];
    const int* steps = (const int*)d_in[7];

    float* out = (float*)d_out;
    const int Btot = in_sizes[0] / 64;     // 262144
    const int blocks = Btot / 64;          // 4096 (64 rows per CTA, 4 warps)

    leapfrog_mma_kernel<<<blocks, THREADS>>>(x, v, f, U, W, Wf, bf, steps, out, Btot);
}